// round 6
// baseline (speedup 1.0000x reference)
#include <cuda_runtime.h>
#include <cstdint>
#include <math.h>

// ---------------- problem dims ----------------
#define NB   8
#define LB   4096
#define HB   1024
#define KB   1024
#define MTOT (NB * LB)          // 32768
#define SEG    32
#define SEGLEN (LB / SEG)       // 128

// ---------------- GEMM tiling -----------------
#define BM 128                  // M rows / CTA
#define BNP 64                  // o-pairs / CTA (B tile = 128 interleaved rows)
#define BKB 64                  // K int8 bytes per stage (64B rows)
#define NKT (KB / BKB)          // 16
#define PIPE 4

// per-stage smem tiles (bytes): 128 rows x 64B each
#define T_A1 0
#define T_A0 8192
#define T_B1 16384
#define T_B0 24576
#define STAGE_BYTES 32768
#define SMEM_DYN (PIPE * STAGE_BYTES)

// ---------------- device scratch ----------------
__device__ float g_a[(size_t)MTOT * HB];   // sigmoid(-z)
__device__ float g_v[(size_t)MTOT * HB];   // sigmoid(z)*g(h_inter)
__device__ float g_Aseg[NB * SEG * HB];
__device__ float g_Bseg[NB * SEG * HB];
__device__ float g_Cin [NB * SEG * HB];
__device__ int8_t g_x1[(size_t)MTOT * KB];     // 32 MB
__device__ int8_t g_x0[(size_t)MTOT * KB];     // 32 MB
__device__ int8_t g_w1[(size_t)2 * HB * KB];   // 2 MB
__device__ int8_t g_w0[(size_t)2 * HB * KB];   // 2 MB

// ---------------- helpers ----------------
__device__ __forceinline__ uint32_t smem_u32(const void* p) {
    uint32_t a;
    asm("{ .reg .u64 t; cvta.to.shared.u64 t, %1; cvt.u32.u64 %0, t; }" : "=r"(a) : "l"(p));
    return a;
}
// 64B-row tile byte offset with XOR swizzle (conflict-free for ldmatrix)
__device__ __forceinline__ uint32_t swz(int row, int chunk) {
    return (uint32_t)(row * 64 + ((chunk ^ ((row >> 1) & 3)) << 4));
}
#define CP_ASYNC16(sdst, gsrc) \
    asm volatile("cp.async.cg.shared.global [%0], [%1], 16;" :: "r"(sdst), "l"(gsrc))
#define CP_COMMIT() asm volatile("cp.async.commit_group;" ::: "memory")
#define CP_WAIT2()  asm volatile("cp.async.wait_group 2;" ::: "memory")
#define CP_WAIT0()  asm volatile("cp.async.wait_group 0;" ::: "memory")

__device__ __forceinline__ void ldmx4(uint32_t* r, uint32_t addr) {
    asm volatile("ldmatrix.sync.aligned.m8n8.x4.shared.b16 {%0,%1,%2,%3}, [%4];"
        : "=r"(r[0]), "=r"(r[1]), "=r"(r[2]), "=r"(r[3]) : "r"(addr));
}
__device__ __forceinline__ void mma_s8(int* c, const uint32_t* a, uint32_t b0, uint32_t b1) {
    asm volatile("mma.sync.aligned.m16n8k32.row.col.s32.s8.s8.s32 "
        "{%0,%1,%2,%3}, {%4,%5,%6,%7}, {%8,%9}, {%0,%1,%2,%3};"
        : "+r"(c[0]), "+r"(c[1]), "+r"(c[2]), "+r"(c[3])
        : "r"(a[0]), "r"(a[1]), "r"(a[2]), "r"(a[3]), "r"(b0), "r"(b1));
}

// ---------------------------------------------------------------------------
// Split fp32 -> 2 int8 digits. x: q=x*16; W: q=w*512. digit1=rn(q), digit0=rn((q-d1)*256)
// ---------------------------------------------------------------------------
template <int SCALE>
__device__ __forceinline__ void split8(const float* f, int8_t* p1, int8_t* p0) {
    #pragma unroll
    for (int j = 0; j < 8; j++) {
        float q = f[j] * (float)SCALE;
        int d1 = __float2int_rn(q);
        d1 = max(-127, min(127, d1));
        float r = q - (float)d1;
        int d0 = __float2int_rn(r * 256.f);
        d0 = max(-127, min(127, d0));
        p1[j] = (int8_t)d1;
        p0[j] = (int8_t)d0;
    }
}
__global__ void __launch_bounds__(256)
split_x_kernel(const float* __restrict__ src)
{
    size_t i = ((size_t)blockIdx.x * 256 + threadIdx.x) * 8;
    float f[8];
    *(float4*)&f[0] = *(const float4*)(src + i);
    *(float4*)&f[4] = *(const float4*)(src + i + 4);
    int8_t p1[8], p0[8];
    split8<16>(f, p1, p0);
    *(uint2*)&g_x1[i] = *(uint2*)p1;
    *(uint2*)&g_x0[i] = *(uint2*)p0;
}
__global__ void __launch_bounds__(256)
split_w_kernel(const float* __restrict__ src)
{
    size_t i = ((size_t)blockIdx.x * 256 + threadIdx.x) * 8;
    float f[8];
    *(float4*)&f[0] = *(const float4*)(src + i);
    *(float4*)&f[4] = *(const float4*)(src + i + 4);
    int8_t p1[8], p0[8];
    split8<512>(f, p1, p0);
    *(uint2*)&g_w1[i] = *(uint2*)p1;
    *(uint2*)&g_w0[i] = *(uint2*)p0;
}

// ---------------------------------------------------------------------------
// int8 2-digit tensor-core GEMM (3 IMMA terms) with fused (a, v) epilogue.
// B tile rows interleave z / h_inter: row j -> W[o0p + (j>>1) + (j&1)*HB].
// z = 2^-13 * sum(X1W1) + 2^-21 * sum(X1W0 + X0W1)
// ---------------------------------------------------------------------------
__global__ void __launch_bounds__(256)
gemm_imma_kernel(const float* __restrict__ b)
{
    extern __shared__ char dynsmem[];
    const uint32_t sbase = smem_u32(dynsmem);

    const int tid = threadIdx.x;
    const int wid = tid >> 5;
    const int l   = tid & 31;
    const int wm  = wid & 3;          // warp m: rows wm*32..+31
    const int wn  = wid >> 2;         // warp n: cols wn*64..+63
    const int m0  = blockIdx.y * BM;
    const int o0p = blockIdx.x * BNP;

    // cp.async source setup: per tile, thread loads entries e = tid*2 + i
    const int8_t *sA1[2], *sA0[2], *sB1[2], *sB0[2];
    uint32_t dst[2];
    #pragma unroll
    for (int i = 0; i < 2; i++) {
        int e = tid * 2 + i;
        int row = e >> 2, ch = e & 3;
        sA1[i] = g_x1 + (size_t)(m0 + row) * KB + ch * 16;
        sA0[i] = g_x0 + (size_t)(m0 + row) * KB + ch * 16;
        int wrow = (row & 1) ? (HB + o0p + (row >> 1)) : (o0p + (row >> 1));
        sB1[i] = g_w1 + (size_t)wrow * KB + ch * 16;
        sB0[i] = g_w0 + (size_t)wrow * KB + ch * 16;
        dst[i] = swz(row, ch);
    }

    int hi[2][8][4], mid[2][8][4];
    #pragma unroll
    for (int a0 = 0; a0 < 2; a0++)
        #pragma unroll
        for (int a1 = 0; a1 < 8; a1++)
            #pragma unroll
            for (int a2 = 0; a2 < 4; a2++) { hi[a0][a1][a2] = 0; mid[a0][a1][a2] = 0; }

    // prologue: fill PIPE-1 stages
    #pragma unroll
    for (int s = 0; s < PIPE - 1; s++) {
        uint32_t st = sbase + s * STAGE_BYTES;
        int ko = s * BKB;
        #pragma unroll
        for (int i = 0; i < 2; i++) {
            CP_ASYNC16(st + T_A1 + dst[i], sA1[i] + ko);
            CP_ASYNC16(st + T_A0 + dst[i], sA0[i] + ko);
            CP_ASYNC16(st + T_B1 + dst[i], sB1[i] + ko);
            CP_ASYNC16(st + T_B0 + dst[i], sB0[i] + ko);
        }
        CP_COMMIT();
    }

    const int lrow  = l & 15;
    const int lchnk = l >> 4;    // 16-byte half select

    for (int kt = 0; kt < NKT; kt++) {
        CP_WAIT2();
        __syncthreads();

        // front-load next-stage loads (target buffer fully consumed last iter)
        int ktn = kt + PIPE - 1;
        if (ktn < NKT) {
            uint32_t stl = sbase + (ktn % PIPE) * STAGE_BYTES;
            int ko = ktn * BKB;
            #pragma unroll
            for (int i = 0; i < 2; i++) {
                CP_ASYNC16(stl + T_A1 + dst[i], sA1[i] + ko);
                CP_ASYNC16(stl + T_A0 + dst[i], sA0[i] + ko);
                CP_ASYNC16(stl + T_B1 + dst[i], sB1[i] + ko);
                CP_ASYNC16(stl + T_B0 + dst[i], sB0[i] + ko);
            }
        }
        CP_COMMIT();   // unconditional: keeps wait_group invariant

        const uint32_t st = sbase + (kt % PIPE) * STAGE_BYTES;
        #pragma unroll
        for (int s = 0; s < 2; s++) {           // two k32 steps per stage
            uint32_t a1[2][4], a0[2][4], b1[4][4], b0[4][4];
            #pragma unroll
            for (int mt = 0; mt < 2; mt++) {
                int row = wm * 32 + mt * 16 + lrow;
                uint32_t off = swz(row, 2 * s + lchnk);
                ldmx4(a1[mt], st + T_A1 + off);
                ldmx4(a0[mt], st + T_A0 + off);
            }
            #pragma unroll
            for (int nt = 0; nt < 4; nt++) {
                int row = wn * 64 + nt * 16 + lrow;
                uint32_t off = swz(row, 2 * s + lchnk);
                ldmx4(b1[nt], st + T_B1 + off);
                ldmx4(b0[nt], st + T_B0 + off);
            }
            #pragma unroll
            for (int mt = 0; mt < 2; mt++)
                #pragma unroll
                for (int nt = 0; nt < 4; nt++) {
                    mma_s8(hi [mt][nt * 2],     a1[mt], b1[nt][0], b1[nt][2]);
                    mma_s8(hi [mt][nt * 2 + 1], a1[mt], b1[nt][1], b1[nt][3]);
                    mma_s8(mid[mt][nt * 2],     a1[mt], b0[nt][0], b0[nt][2]);
                    mma_s8(mid[mt][nt * 2 + 1], a1[mt], b0[nt][1], b0[nt][3]);
                    mma_s8(mid[mt][nt * 2],     a0[mt], b1[nt][0], b1[nt][2]);
                    mma_s8(mid[mt][nt * 2 + 1], a0[mt], b1[nt][1], b1[nt][3]);
                }
        }
    }
    CP_WAIT0();

    // ------------- epilogue: even col = z, odd col = h_inter of same o
    const float C_HI = 0x1p-13f, C_MID = 0x1p-21f;
    #pragma unroll
    for (int mt = 0; mt < 2; mt++) {
        #pragma unroll
        for (int nt8 = 0; nt8 < 8; nt8++) {
            int o = o0p + wn * 32 + nt8 * 4 + (l & 3);
            float bz  = __ldg(b + o);
            float bh_ = __ldg(b + HB + o);
            #pragma unroll
            for (int half = 0; half < 2; half++) {
                int m = m0 + wm * 32 + mt * 16 + (l >> 2) + half * 8;
                float z  = (float)hi[mt][nt8][half * 2]     * C_HI
                         + (float)mid[mt][nt8][half * 2]    * C_MID + bz;
                float hin = (float)hi[mt][nt8][half * 2 + 1] * C_HI
                          + (float)mid[mt][nt8][half * 2 + 1]* C_MID + bh_;
                float t   = __expf(-fabsf(z));
                float inv = 1.0f / (1.0f + t);
                float sig = (z >= 0.f) ? inv : t * inv;   // sigmoid(z)
                float a   = (z >= 0.f) ? t * inv : inv;   // sigmoid(-z)
                float gt;
                if (hin >= 0.f) gt = hin + 0.5f;
                else { float t2 = __expf(hin); gt = t2 / (1.f + t2); }
                size_t idx = (size_t)m * HB + o;
                g_a[idx] = a;
                g_v[idx] = sig * gt;
            }
        }
    }
}

// ---------------------------------------------------------------------------
// Scan passes
// ---------------------------------------------------------------------------
__global__ void __launch_bounds__(256)
scan_pass1(void)
{
    int h   = blockIdx.x * 256 + threadIdx.x;
    int seg = blockIdx.y;
    int n   = blockIdx.z;
    size_t base = ((size_t)(n * LB + seg * SEGLEN)) * HB + h;
    float A = 1.f, B = 0.f;
    #pragma unroll 4
    for (int i = 0; i < SEGLEN; i++) {
        float a = g_a[base + (size_t)i * HB];
        float v = g_v[base + (size_t)i * HB];
        B = fmaf(a, B, v);
        A *= a;
    }
    int idx = (n * SEG + seg) * HB + h;
    g_Aseg[idx] = A;
    g_Bseg[idx] = B;
}

__global__ void __launch_bounds__(256)
scan_pass2(const float* __restrict__ hx)
{
    int h = blockIdx.x * 256 + threadIdx.x;
    int n = blockIdx.y;
    float hcur = hx[n * HB + h];
    for (int s = 0; s < SEG; s++) {
        int idx = (n * SEG + s) * HB + h;
        g_Cin[idx] = hcur;
        hcur = fmaf(g_Aseg[idx], hcur, g_Bseg[idx]);
    }
}

__global__ void __launch_bounds__(256)
scan_pass3(float* __restrict__ out)
{
    int h   = blockIdx.x * 256 + threadIdx.x;
    int seg = blockIdx.y;
    int n   = blockIdx.z;
    size_t base = ((size_t)(n * LB + seg * SEGLEN)) * HB + h;
    float hcur = g_Cin[(n * SEG + seg) * HB + h];
    #pragma unroll 4
    for (int i = 0; i < SEGLEN; i++) {
        float a = g_a[base + (size_t)i * HB];
        float v = g_v[base + (size_t)i * HB];
        hcur = fmaf(a, hcur, v);
        out[base + (size_t)i * HB] = hcur;
    }
}

// ---------------------------------------------------------------------------
extern "C" void kernel_launch(void* const* d_in, const int* in_sizes, int n_in,
                              void* d_out, int out_size)
{
    const float *x = nullptr, *W = nullptr, *b = nullptr, *hx = nullptr;
    for (int i = 0; i < n_in; i++) {
        switch (in_sizes[i]) {
            case 33554432: x  = (const float*)d_in[i]; break;
            case 2097152:  W  = (const float*)d_in[i]; break;
            case 2048:     b  = (const float*)d_in[i]; break;
            case 8192:     hx = (const float*)d_in[i]; break;
        }
    }
    float* out = (float*)d_out;

    cudaFuncSetAttribute(gemm_imma_kernel, cudaFuncAttributeMaxDynamicSharedMemorySize, SMEM_DYN);

    split_x_kernel<<<(size_t)MTOT * KB / 8 / 256, 256>>>(x);
    split_w_kernel<<<(size_t)2 * HB * KB / 8 / 256, 256>>>(W);

    dim3 gemm_grid(HB / BNP, MTOT / BM);   // (16, 256), x fastest -> A panel L2 reuse
    gemm_imma_kernel<<<gemm_grid, 256, SMEM_DYN>>>(b);

    scan_pass1<<<dim3(HB / 256, SEG, NB), 256>>>();
    scan_pass2<<<dim3(HB / 256, NB), 256>>>(hx);
    scan_pass3<<<dim3(HB / 256, SEG, NB), 256>>>(out);
}

// round 8
// speedup vs baseline: 2.5664x; 2.5664x over previous
#include <cuda_runtime.h>
#include <cuda_fp16.h>
#include <cstdint>
#include <math.h>

// ---------------- problem dims ----------------
#define NB   8
#define LB   4096
#define HB   1024
#define KB   1024
#define MTOT (NB * LB)          // 32768
#define SEG    32
#define SEGLEN (LB / SEG)       // 128

// ---------------- GEMM tiling -----------------
#define BM 128                  // M rows / CTA
#define BNP 64                  // o-pairs / CTA (B tile = 128 interleaved rows)
#define BKE 64                  // K fp16 elems per stage (128B rows)
#define NKT (KB / BKE)          // 16
#define PIPE 4

// per-stage smem tiles (bytes): 128 rows x 128B each
#define T_A  0
#define T_BH 16384
#define T_BL 32768
#define STAGE_BYTES 49152
#define SMEM_DYN (PIPE * STAGE_BYTES)   // 192 KB

// ---------------- device scratch ----------------
__device__ float g_a[(size_t)MTOT * HB];   // sigmoid(-z)
__device__ float g_v[(size_t)MTOT * HB];   // sigmoid(z)*g(h_inter)
__device__ float g_Aseg[NB * SEG * HB];
__device__ float g_Bseg[NB * SEG * HB];
__device__ float g_Cin [NB * SEG * HB];
__device__ __half g_xh[(size_t)MTOT * KB];     // 64 MB
__device__ __half g_wh[(size_t)2 * HB * KB];   // 4 MB
__device__ __half g_wl[(size_t)2 * HB * KB];   // 4 MB  (scaled residual * 2^11)

// ---------------- helpers ----------------
__device__ __forceinline__ uint32_t smem_u32(const void* p) {
    uint32_t a;
    asm("{ .reg .u64 t; cvta.to.shared.u64 t, %1; cvt.u32.u64 %0, t; }" : "=r"(a) : "l"(p));
    return a;
}
// 128B-row tile offset, 16B chunk XOR swizzle (conflict-free ldmatrix + cp.async)
__device__ __forceinline__ uint32_t swz(int row, int ch) {
    return (uint32_t)(row * 128 + ((ch ^ (row & 7)) << 4));
}
#define CP_ASYNC16(sdst, gsrc) \
    asm volatile("cp.async.cg.shared.global [%0], [%1], 16;" :: "r"(sdst), "l"(gsrc))
#define CP_COMMIT() asm volatile("cp.async.commit_group;" ::: "memory")
#define CP_WAIT2()  asm volatile("cp.async.wait_group 2;" ::: "memory")
#define CP_WAIT0()  asm volatile("cp.async.wait_group 0;" ::: "memory")

__device__ __forceinline__ void ldmx4(uint32_t* r, uint32_t addr) {
    asm volatile("ldmatrix.sync.aligned.m8n8.x4.shared.b16 {%0,%1,%2,%3}, [%4];"
        : "=r"(r[0]), "=r"(r[1]), "=r"(r[2]), "=r"(r[3]) : "r"(addr));
}
__device__ __forceinline__ void mma_f16(float* c, const uint32_t* a, uint32_t b0, uint32_t b1) {
    asm volatile("mma.sync.aligned.m16n8k16.row.col.f32.f16.f16.f32 "
        "{%0,%1,%2,%3}, {%4,%5,%6,%7}, {%8,%9}, {%0,%1,%2,%3};"
        : "+f"(c[0]), "+f"(c[1]), "+f"(c[2]), "+f"(c[3])
        : "r"(a[0]), "r"(a[1]), "r"(a[2]), "r"(a[3]), "r"(b0), "r"(b1));
}

// ---------------------------------------------------------------------------
// Conversions: x -> fp16 (4 chunked launches);  W -> fp16 hi + scaled residual
// ---------------------------------------------------------------------------
__global__ void __launch_bounds__(256)
split_x_kernel(const float* __restrict__ src, int chunk)
{
    size_t i = ((size_t)blockIdx.x * 256 + threadIdx.x) * 8
             + (size_t)chunk * ((size_t)MTOT * KB / 4);
    float f[8];
    *(float4*)&f[0] = *(const float4*)(src + i);
    *(float4*)&f[4] = *(const float4*)(src + i + 4);
    __half h[8];
    #pragma unroll
    for (int j = 0; j < 8; j++) h[j] = __float2half_rn(f[j]);
    *(uint4*)&g_xh[i] = *(uint4*)h;
}
__global__ void __launch_bounds__(256)
split_w_kernel(const float* __restrict__ src)
{
    size_t i = ((size_t)blockIdx.x * 256 + threadIdx.x) * 8;
    float f[8];
    *(float4*)&f[0] = *(const float4*)(src + i);
    *(float4*)&f[4] = *(const float4*)(src + i + 4);
    __half h[8], l[8];
    #pragma unroll
    for (int j = 0; j < 8; j++) {
        h[j] = __float2half_rn(f[j]);
        l[j] = __float2half_rn((f[j] - __half2float(h[j])) * 2048.0f);
    }
    *(uint4*)&g_wh[i] = *(uint4*)h;
    *(uint4*)&g_wl[i] = *(uint4*)l;
}

// ---------------------------------------------------------------------------
// fp16 2-term tensor-core GEMM with fused (a, v) epilogue.
// B tile rows interleave z / h_inter: row j -> W[o0p + (j>>1) + (j&1)*HB].
// z = sum(x*wh) + 2^-11 * sum(x*wl) + b
// ---------------------------------------------------------------------------
__global__ void __launch_bounds__(256)
gemm_hmma_kernel(const float* __restrict__ b)
{
    extern __shared__ char dynsmem[];
    const uint32_t sbase = smem_u32(dynsmem);

    const int tid = threadIdx.x;
    const int wid = tid >> 5;
    const int l   = tid & 31;
    const int wm  = wid & 3;          // warp m: rows wm*32..+31
    const int wn  = wid >> 2;         // warp n: B rows wn*64..+63
    const int m0  = blockIdx.y * BM;
    const int o0p = blockIdx.x * BNP;

    // cp.async mapping: per tile, thread loads entries e = tid*4 + i (1024 total)
    const __half *sA[4], *sBH[4], *sBL[4];
    uint32_t dst[4];
    #pragma unroll
    for (int i = 0; i < 4; i++) {
        int e = tid * 4 + i;
        int row = e >> 3, ch = e & 7;
        sA[i] = g_xh + (size_t)(m0 + row) * KB + ch * 8;
        int wrow = (row & 1) ? (HB + o0p + (row >> 1)) : (o0p + (row >> 1));
        sBH[i] = g_wh + (size_t)wrow * KB + ch * 8;
        sBL[i] = g_wl + (size_t)wrow * KB + ch * 8;
        dst[i] = swz(row, ch);
    }

    float hi[2][8][4], mid[2][8][4];
    #pragma unroll
    for (int a0 = 0; a0 < 2; a0++)
        #pragma unroll
        for (int a1 = 0; a1 < 8; a1++)
            #pragma unroll
            for (int a2 = 0; a2 < 4; a2++) { hi[a0][a1][a2] = 0.f; mid[a0][a1][a2] = 0.f; }

    // prologue: fill PIPE-1 stages
    #pragma unroll
    for (int s = 0; s < PIPE - 1; s++) {
        uint32_t st = sbase + s * STAGE_BYTES;
        int ko = s * BKE;
        #pragma unroll
        for (int i = 0; i < 4; i++) {
            CP_ASYNC16(st + T_A  + dst[i], sA[i]  + ko);
            CP_ASYNC16(st + T_BH + dst[i], sBH[i] + ko);
            CP_ASYNC16(st + T_BL + dst[i], sBL[i] + ko);
        }
        CP_COMMIT();
    }

    const int lrow  = l & 15;
    const int lchnk = l >> 4;    // 16B half of the 32B k16 slice

    for (int kt = 0; kt < NKT; kt++) {
        CP_WAIT2();
        __syncthreads();

        // front-load next-stage loads (target buffer consumed last iteration)
        int ktn = kt + PIPE - 1;
        if (ktn < NKT) {
            uint32_t stl = sbase + (ktn % PIPE) * STAGE_BYTES;
            int ko = ktn * BKE;
            #pragma unroll
            for (int i = 0; i < 4; i++) {
                CP_ASYNC16(stl + T_A  + dst[i], sA[i]  + ko);
                CP_ASYNC16(stl + T_BH + dst[i], sBH[i] + ko);
                CP_ASYNC16(stl + T_BL + dst[i], sBL[i] + ko);
            }
        }
        CP_COMMIT();   // unconditional: keeps wait_group invariant

        const uint32_t st = sbase + (kt % PIPE) * STAGE_BYTES;
        #pragma unroll
        for (int s = 0; s < 4; s++) {           // four k16 steps per stage
            uint32_t a[2][4], bh[4][4], bl[4][4];
            #pragma unroll
            for (int mt = 0; mt < 2; mt++) {
                int row = wm * 32 + mt * 16 + lrow;
                ldmx4(a[mt], st + T_A + swz(row, 2 * s + lchnk));
            }
            #pragma unroll
            for (int nt = 0; nt < 4; nt++) {
                int row = wn * 64 + nt * 16 + lrow;
                uint32_t off = swz(row, 2 * s + lchnk);
                ldmx4(bh[nt], st + T_BH + off);
                ldmx4(bl[nt], st + T_BL + off);
            }
            #pragma unroll
            for (int mt = 0; mt < 2; mt++)
                #pragma unroll
                for (int nt = 0; nt < 4; nt++) {
                    mma_f16(hi [mt][nt * 2],     a[mt], bh[nt][0], bh[nt][2]);
                    mma_f16(hi [mt][nt * 2 + 1], a[mt], bh[nt][1], bh[nt][3]);
                    mma_f16(mid[mt][nt * 2],     a[mt], bl[nt][0], bl[nt][2]);
                    mma_f16(mid[mt][nt * 2 + 1], a[mt], bl[nt][1], bl[nt][3]);
                }
        }
    }
    CP_WAIT0();

    // ------------- epilogue: even B-row = z, odd = h_inter of same o
    const float C_MID = 0x1p-11f;
    #pragma unroll
    for (int mt = 0; mt < 2; mt++) {
        #pragma unroll
        for (int nt8 = 0; nt8 < 8; nt8++) {
            int o = o0p + wn * 32 + nt8 * 4 + (l & 3);
            float bz  = __ldg(b + o);
            float bh_ = __ldg(b + HB + o);
            #pragma unroll
            for (int half = 0; half < 2; half++) {
                int m = m0 + wm * 32 + mt * 16 + (l >> 2) + half * 8;
                float z   = hi[mt][nt8][half * 2]     + C_MID * mid[mt][nt8][half * 2]     + bz;
                float hin = hi[mt][nt8][half * 2 + 1] + C_MID * mid[mt][nt8][half * 2 + 1] + bh_;
                float t   = __expf(-fabsf(z));
                float inv = 1.0f / (1.0f + t);
                float sig = (z >= 0.f) ? inv : t * inv;   // sigmoid(z)
                float av  = (z >= 0.f) ? t * inv : inv;   // sigmoid(-z)
                float gt;
                if (hin >= 0.f) gt = hin + 0.5f;
                else { float t2 = __expf(hin); gt = t2 / (1.f + t2); }
                size_t idx = (size_t)m * HB + o;
                g_a[idx] = av;
                g_v[idx] = sig * gt;
            }
        }
    }
}

// ---------------------------------------------------------------------------
// Scan passes
// ---------------------------------------------------------------------------
__global__ void __launch_bounds__(256)
scan_pass1(void)
{
    int h   = blockIdx.x * 256 + threadIdx.x;
    int seg = blockIdx.y;
    int n   = blockIdx.z;
    size_t base = ((size_t)(n * LB + seg * SEGLEN)) * HB + h;
    float A = 1.f, B = 0.f;
    #pragma unroll 4
    for (int i = 0; i < SEGLEN; i++) {
        float a = g_a[base + (size_t)i * HB];
        float v = g_v[base + (size_t)i * HB];
        B = fmaf(a, B, v);
        A *= a;
    }
    int idx = (n * SEG + seg) * HB + h;
    g_Aseg[idx] = A;
    g_Bseg[idx] = B;
}

__global__ void __launch_bounds__(256)
scan_pass2(const float* __restrict__ hx)
{
    int h = blockIdx.x * 256 + threadIdx.x;
    int n = blockIdx.y;
    float hcur = hx[n * HB + h];
    for (int s = 0; s < SEG; s++) {
        int idx = (n * SEG + s) * HB + h;
        g_Cin[idx] = hcur;
        hcur = fmaf(g_Aseg[idx], hcur, g_Bseg[idx]);
    }
}

__global__ void __launch_bounds__(256)
scan_pass3(float* __restrict__ out)
{
    int h   = blockIdx.x * 256 + threadIdx.x;
    int seg = blockIdx.y;
    int n   = blockIdx.z;
    size_t base = ((size_t)(n * LB + seg * SEGLEN)) * HB + h;
    float hcur = g_Cin[(n * SEG + seg) * HB + h];
    #pragma unroll 4
    for (int i = 0; i < SEGLEN; i++) {
        float a = g_a[base + (size_t)i * HB];
        float v = g_v[base + (size_t)i * HB];
        hcur = fmaf(a, hcur, v);
        out[base + (size_t)i * HB] = hcur;
    }
}

// ---------------------------------------------------------------------------
extern "C" void kernel_launch(void* const* d_in, const int* in_sizes, int n_in,
                              void* d_out, int out_size)
{
    const float *x = nullptr, *W = nullptr, *b = nullptr, *hx = nullptr;
    for (int i = 0; i < n_in; i++) {
        switch (in_sizes[i]) {
            case 33554432: x  = (const float*)d_in[i]; break;
            case 2097152:  W  = (const float*)d_in[i]; break;
            case 2048:     b  = (const float*)d_in[i]; break;
            case 8192:     hx = (const float*)d_in[i]; break;
        }
    }
    float* out = (float*)d_out;

    cudaFuncSetAttribute(gemm_hmma_kernel, cudaFuncAttributeMaxDynamicSharedMemorySize, SMEM_DYN);

    // launches 1-5 before the GEMM so position-based ncu capture hits the GEMM
    split_w_kernel<<<(size_t)2 * HB * KB / 8 / 256, 256>>>(W);
    const size_t xq = (size_t)MTOT * KB / 4 / 8 / 256;   // 4096 blocks per quarter
    split_x_kernel<<<xq, 256>>>(x, 0);
    split_x_kernel<<<xq, 256>>>(x, 1);
    split_x_kernel<<<xq, 256>>>(x, 2);
    split_x_kernel<<<xq, 256>>>(x, 3);

    dim3 gemm_grid(HB / BNP, MTOT / BM);   // (16, 256)
    gemm_hmma_kernel<<<gemm_grid, 256, SMEM_DYN>>>(b);

    scan_pass1<<<dim3(HB / 256, SEG, NB), 256>>>();
    scan_pass2<<<dim3(HB / 256, NB), 256>>>(hx);
    scan_pass3<<<dim3(HB / 256, SEG, NB), 256>>>(out);
}

// round 9
// speedup vs baseline: 3.6170x; 1.4094x over previous
#include <cuda_runtime.h>
#include <cuda_fp16.h>
#include <cstdint>
#include <math.h>

// ---------------- problem dims ----------------
#define NB   8
#define LB   4096
#define HB   1024
#define KB   1024
#define MTOT (NB * LB)          // 32768
#define SEG    32
#define SEGLEN (LB / SEG)       // 128

// ---------------- GEMM tiling -----------------
#define BM 128                  // M rows / CTA
#define BNP 64                  // o-pairs / CTA (B tile = 128 interleaved rows)
#define BKE 64                  // K fp16 elems per stage (128B rows)
#define NKT (KB / BKE)          // 16
#define PIPE 4

// per-stage smem tiles (bytes): 128 rows x 128B each
#define T_A  0
#define T_B  16384
#define STAGE_BYTES 32768
#define SMEM_DYN (PIPE * STAGE_BYTES)   // 128 KB

// ---------------- device scratch ----------------
__device__ float g_a[(size_t)MTOT * HB];   // sigmoid(-z)
__device__ float g_v[(size_t)MTOT * HB];   // sigmoid(z)*g(h_inter)
__device__ float g_Aseg[NB * SEG * HB];
__device__ float g_Bseg[NB * SEG * HB];
__device__ float g_Cin [NB * SEG * HB];
__device__ __half g_xh[(size_t)MTOT * KB];     // 64 MB
__device__ __half g_wh[(size_t)2 * HB * KB];   // 4 MB

// ---------------- helpers ----------------
__device__ __forceinline__ uint32_t smem_u32(const void* p) {
    uint32_t a;
    asm("{ .reg .u64 t; cvta.to.shared.u64 t, %1; cvt.u32.u64 %0, t; }" : "=r"(a) : "l"(p));
    return a;
}
// 128B-row tile offset, 16B chunk XOR swizzle (conflict-free ldmatrix + cp.async)
__device__ __forceinline__ uint32_t swz(int row, int ch) {
    return (uint32_t)(row * 128 + ((ch ^ (row & 7)) << 4));
}
#define CP_ASYNC16(sdst, gsrc) \
    asm volatile("cp.async.cg.shared.global [%0], [%1], 16;" :: "r"(sdst), "l"(gsrc))
#define CP_COMMIT() asm volatile("cp.async.commit_group;" ::: "memory")
#define CP_WAIT2()  asm volatile("cp.async.wait_group 2;" ::: "memory")
#define CP_WAIT0()  asm volatile("cp.async.wait_group 0;" ::: "memory")

__device__ __forceinline__ void ldmx4(uint32_t* r, uint32_t addr) {
    asm volatile("ldmatrix.sync.aligned.m8n8.x4.shared.b16 {%0,%1,%2,%3}, [%4];"
        : "=r"(r[0]), "=r"(r[1]), "=r"(r[2]), "=r"(r[3]) : "r"(addr));
}
__device__ __forceinline__ void mma_f16(float* c, const uint32_t* a, uint32_t b0, uint32_t b1) {
    asm volatile("mma.sync.aligned.m16n8k16.row.col.f32.f16.f16.f32 "
        "{%0,%1,%2,%3}, {%4,%5,%6,%7}, {%8,%9}, {%0,%1,%2,%3};"
        : "+f"(c[0]), "+f"(c[1]), "+f"(c[2]), "+f"(c[3])
        : "r"(a[0]), "r"(a[1]), "r"(a[2]), "r"(a[3]), "r"(b0), "r"(b1));
}

// ---------------------------------------------------------------------------
// Conversions to fp16 (rn)
// ---------------------------------------------------------------------------
__global__ void __launch_bounds__(256)
conv_x_kernel(const float* __restrict__ src, int chunk)
{
    size_t i = ((size_t)blockIdx.x * 256 + threadIdx.x) * 8
             + (size_t)chunk * ((size_t)MTOT * KB / 4);
    float f[8];
    *(float4*)&f[0] = *(const float4*)(src + i);
    *(float4*)&f[4] = *(const float4*)(src + i + 4);
    __half h[8];
    #pragma unroll
    for (int j = 0; j < 8; j++) h[j] = __float2half_rn(f[j]);
    *(uint4*)&g_xh[i] = *(uint4*)h;
}
__global__ void __launch_bounds__(256)
conv_w_kernel(const float* __restrict__ src)
{
    size_t i = ((size_t)blockIdx.x * 256 + threadIdx.x) * 8;
    float f[8];
    *(float4*)&f[0] = *(const float4*)(src + i);
    *(float4*)&f[4] = *(const float4*)(src + i + 4);
    __half h[8];
    #pragma unroll
    for (int j = 0; j < 8; j++) h[j] = __float2half_rn(f[j]);
    *(uint4*)&g_wh[i] = *(uint4*)h;
}

// ---------------------------------------------------------------------------
// fp16 single-term tensor-core GEMM with fused (a, v) epilogue.
// B tile rows interleave z / h_inter: row j -> W[o0p + (j>>1) + (j&1)*HB].
// ---------------------------------------------------------------------------
__global__ void __launch_bounds__(256)
gemm_hmma_kernel(const float* __restrict__ b)
{
    extern __shared__ char dynsmem[];
    const uint32_t sbase = smem_u32(dynsmem);

    const int tid = threadIdx.x;
    const int wid = tid >> 5;
    const int l   = tid & 31;
    const int wm  = wid & 3;          // warp m: rows wm*32..+31
    const int wn  = wid >> 2;         // warp n: B rows wn*64..+63
    const int m0  = blockIdx.y * BM;
    const int o0p = blockIdx.x * BNP;

    // cp.async mapping: per tile, thread loads entries e = tid*4 + i (1024 total)
    const __half *sA[4], *sB[4];
    uint32_t dst[4];
    #pragma unroll
    for (int i = 0; i < 4; i++) {
        int e = tid * 4 + i;
        int row = e >> 3, ch = e & 7;
        sA[i] = g_xh + (size_t)(m0 + row) * KB + ch * 8;
        int wrow = (row & 1) ? (HB + o0p + (row >> 1)) : (o0p + (row >> 1));
        sB[i] = g_wh + (size_t)wrow * KB + ch * 8;
        dst[i] = swz(row, ch);
    }

    float acc[2][8][4];
    #pragma unroll
    for (int a0 = 0; a0 < 2; a0++)
        #pragma unroll
        for (int a1 = 0; a1 < 8; a1++)
            #pragma unroll
            for (int a2 = 0; a2 < 4; a2++) acc[a0][a1][a2] = 0.f;

    // prologue: fill PIPE-1 stages
    #pragma unroll
    for (int s = 0; s < PIPE - 1; s++) {
        uint32_t st = sbase + s * STAGE_BYTES;
        int ko = s * BKE;
        #pragma unroll
        for (int i = 0; i < 4; i++) {
            CP_ASYNC16(st + T_A + dst[i], sA[i] + ko);
            CP_ASYNC16(st + T_B + dst[i], sB[i] + ko);
        }
        CP_COMMIT();
    }

    const int lrow  = l & 15;
    const int lchnk = l >> 4;    // 16B half of the 32B k16 slice

    for (int kt = 0; kt < NKT; kt++) {
        CP_WAIT2();
        __syncthreads();

        // front-load next-stage loads (target buffer consumed last iteration)
        int ktn = kt + PIPE - 1;
        if (ktn < NKT) {
            uint32_t stl = sbase + (ktn % PIPE) * STAGE_BYTES;
            int ko = ktn * BKE;
            #pragma unroll
            for (int i = 0; i < 4; i++) {
                CP_ASYNC16(stl + T_A + dst[i], sA[i] + ko);
                CP_ASYNC16(stl + T_B + dst[i], sB[i] + ko);
            }
        }
        CP_COMMIT();   // unconditional: keeps wait_group invariant

        const uint32_t st = sbase + (kt % PIPE) * STAGE_BYTES;
        #pragma unroll
        for (int s = 0; s < 4; s++) {           // four k16 steps per stage
            uint32_t a[2][4], bm[4][4];
            #pragma unroll
            for (int mt = 0; mt < 2; mt++) {
                int row = wm * 32 + mt * 16 + lrow;
                ldmx4(a[mt], st + T_A + swz(row, 2 * s + lchnk));
            }
            #pragma unroll
            for (int nt = 0; nt < 4; nt++) {
                int row = wn * 64 + nt * 16 + lrow;
                ldmx4(bm[nt], st + T_B + swz(row, 2 * s + lchnk));
            }
            #pragma unroll
            for (int mt = 0; mt < 2; mt++)
                #pragma unroll
                for (int nt = 0; nt < 4; nt++) {
                    mma_f16(acc[mt][nt * 2],     a[mt], bm[nt][0], bm[nt][2]);
                    mma_f16(acc[mt][nt * 2 + 1], a[mt], bm[nt][1], bm[nt][3]);
                }
        }
    }
    CP_WAIT0();

    // ------------- epilogue: even B-row = z, odd = h_inter of same o
    #pragma unroll
    for (int mt = 0; mt < 2; mt++) {
        #pragma unroll
        for (int nt8 = 0; nt8 < 8; nt8++) {
            int o = o0p + wn * 32 + nt8 * 4 + (l & 3);
            float bz  = __ldg(b + o);
            float bh_ = __ldg(b + HB + o);
            #pragma unroll
            for (int half = 0; half < 2; half++) {
                int m = m0 + wm * 32 + mt * 16 + (l >> 2) + half * 8;
                float z   = acc[mt][nt8][half * 2]     + bz;
                float hin = acc[mt][nt8][half * 2 + 1] + bh_;
                float t   = __expf(-fabsf(z));
                float inv = 1.0f / (1.0f + t);
                float sig = (z >= 0.f) ? inv : t * inv;   // sigmoid(z)
                float av  = (z >= 0.f) ? t * inv : inv;   // sigmoid(-z)
                float gt;
                if (hin >= 0.f) gt = hin + 0.5f;
                else { float t2 = __expf(hin); gt = t2 / (1.f + t2); }
                size_t idx = (size_t)m * HB + o;
                g_a[idx] = av;
                g_v[idx] = sig * gt;
            }
        }
    }
}

// ---------------------------------------------------------------------------
// Scan passes
// ---------------------------------------------------------------------------
__global__ void __launch_bounds__(256)
scan_pass1(void)
{
    int h   = blockIdx.x * 256 + threadIdx.x;
    int seg = blockIdx.y;
    int n   = blockIdx.z;
    size_t base = ((size_t)(n * LB + seg * SEGLEN)) * HB + h;
    float A = 1.f, B = 0.f;
    #pragma unroll 4
    for (int i = 0; i < SEGLEN; i++) {
        float a = g_a[base + (size_t)i * HB];
        float v = g_v[base + (size_t)i * HB];
        B = fmaf(a, B, v);
        A *= a;
    }
    int idx = (n * SEG + seg) * HB + h;
    g_Aseg[idx] = A;
    g_Bseg[idx] = B;
}

__global__ void __launch_bounds__(256)
scan_pass2(const float* __restrict__ hx)
{
    int h = blockIdx.x * 256 + threadIdx.x;
    int n = blockIdx.y;
    float hcur = hx[n * HB + h];
    for (int s = 0; s < SEG; s++) {
        int idx = (n * SEG + s) * HB + h;
        g_Cin[idx] = hcur;
        hcur = fmaf(g_Aseg[idx], hcur, g_Bseg[idx]);
    }
}

__global__ void __launch_bounds__(256)
scan_pass3(float* __restrict__ out)
{
    int h   = blockIdx.x * 256 + threadIdx.x;
    int seg = blockIdx.y;
    int n   = blockIdx.z;
    size_t base = ((size_t)(n * LB + seg * SEGLEN)) * HB + h;
    float hcur = g_Cin[(n * SEG + seg) * HB + h];
    #pragma unroll 4
    for (int i = 0; i < SEGLEN; i++) {
        float a = g_a[base + (size_t)i * HB];
        float v = g_v[base + (size_t)i * HB];
        hcur = fmaf(a, hcur, v);
        out[base + (size_t)i * HB] = hcur;
    }
}

// ---------------------------------------------------------------------------
extern "C" void kernel_launch(void* const* d_in, const int* in_sizes, int n_in,
                              void* d_out, int out_size)
{
    const float *x = nullptr, *W = nullptr, *b = nullptr, *hx = nullptr;
    for (int i = 0; i < n_in; i++) {
        switch (in_sizes[i]) {
            case 33554432: x  = (const float*)d_in[i]; break;
            case 2097152:  W  = (const float*)d_in[i]; break;
            case 2048:     b  = (const float*)d_in[i]; break;
            case 8192:     hx = (const float*)d_in[i]; break;
        }
    }
    float* out = (float*)d_out;

    cudaFuncSetAttribute(gemm_hmma_kernel, cudaFuncAttributeMaxDynamicSharedMemorySize, SMEM_DYN);

    // launches 1-5 before the GEMM (position-based ncu capture lands on GEMM)
    conv_w_kernel<<<(size_t)2 * HB * KB / 8 / 256, 256>>>(W);
    const size_t xq = (size_t)MTOT * KB / 4 / 8 / 256;   // 4096 blocks per quarter
    conv_x_kernel<<<xq, 256>>>(x, 0);
    conv_x_kernel<<<xq, 256>>>(x, 1);
    conv_x_kernel<<<xq, 256>>>(x, 2);
    conv_x_kernel<<<xq, 256>>>(x, 3);

    dim3 gemm_grid(HB / BNP, MTOT / BM);   // (16, 256)
    gemm_hmma_kernel<<<gemm_grid, 256, SMEM_DYN>>>(b);

    scan_pass1<<<dim3(HB / 256, SEG, NB), 256>>>();
    scan_pass2<<<dim3(HB / 256, NB), 256>>>(hx);
    scan_pass3<<<dim3(HB / 256, SEG, NB), 256>>>(out);
}

// round 11
// speedup vs baseline: 4.4782x; 1.2381x over previous
#include <cuda_runtime.h>
#include <cuda_fp16.h>
#include <cstdint>
#include <math.h>

// ---------------- problem dims ----------------
#define NB   8
#define LB   4096
#define HB   1024
#define KB   1024
#define MTOT (NB * LB)          // 32768
#define SEG    32
#define SEGLEN (LB / SEG)       // 128

// ---------------- GEMM tiling -----------------
#define BM 128                  // M rows / CTA
#define BNP 64                  // o-pairs / CTA (B tile = 128 interleaved rows)
#define BKE 64                  // K fp16 elems per stage (128B rows)
#define NKT (KB / BKE)          // 16
#define PIPE 3

// per-stage smem tiles (bytes): 128 rows x 128B each
#define T_A  0
#define T_B  16384
#define STAGE_BYTES 32768
#define SMEM_DYN (PIPE * STAGE_BYTES)   // 96 KB -> 2 CTAs/SM

// ---------------- device scratch ----------------
__device__ float g_a[(size_t)MTOT * HB];   // sigmoid(-z)
__device__ float g_v[(size_t)MTOT * HB];   // sigmoid(z)*g(h_inter)
__device__ float g_Aseg[NB * SEG * HB];
__device__ float g_Bseg[NB * SEG * HB];
__device__ float g_Cin [NB * SEG * HB];
__device__ __half g_xh[(size_t)MTOT * KB];     // 64 MB
__device__ __half g_wh[(size_t)2 * HB * KB];   // 4 MB

// ---------------- helpers ----------------
__device__ __forceinline__ uint32_t smem_u32(const void* p) {
    uint32_t a;
    asm("{ .reg .u64 t; cvta.to.shared.u64 t, %1; cvt.u32.u64 %0, t; }" : "=r"(a) : "l"(p));
    return a;
}
// 128B-row tile offset, 16B chunk XOR swizzle (conflict-free ldmatrix + cp.async)
__device__ __forceinline__ uint32_t swz(int row, int ch) {
    return (uint32_t)(row * 128 + ((ch ^ (row & 7)) << 4));
}
#define CP_ASYNC16(sdst, gsrc) \
    asm volatile("cp.async.cg.shared.global [%0], [%1], 16;" :: "r"(sdst), "l"(gsrc))
#define CP_COMMIT() asm volatile("cp.async.commit_group;" ::: "memory")
#define CP_WAIT1()  asm volatile("cp.async.wait_group 1;" ::: "memory")
#define CP_WAIT0()  asm volatile("cp.async.wait_group 0;" ::: "memory")

__device__ __forceinline__ void ldmx4(uint32_t* r, uint32_t addr) {
    asm volatile("ldmatrix.sync.aligned.m8n8.x4.shared.b16 {%0,%1,%2,%3}, [%4];"
        : "=r"(r[0]), "=r"(r[1]), "=r"(r[2]), "=r"(r[3]) : "r"(addr));
}
__device__ __forceinline__ void mma_f16(float* c, const uint32_t* a, uint32_t b0, uint32_t b1) {
    asm volatile("mma.sync.aligned.m16n8k16.row.col.f32.f16.f16.f32 "
        "{%0,%1,%2,%3}, {%4,%5,%6,%7}, {%8,%9}, {%0,%1,%2,%3};"
        : "+f"(c[0]), "+f"(c[1]), "+f"(c[2]), "+f"(c[3])
        : "r"(a[0]), "r"(a[1]), "r"(a[2]), "r"(a[3]), "r"(b0), "r"(b1));
}

// ---------------------------------------------------------------------------
// Conversions to fp16 (rn)
// ---------------------------------------------------------------------------
__global__ void __launch_bounds__(256)
conv_x_kernel(const float* __restrict__ src, int chunk)
{
    size_t i = ((size_t)blockIdx.x * 256 + threadIdx.x) * 8
             + (size_t)chunk * ((size_t)MTOT * KB / 4);
    float f[8];
    *(float4*)&f[0] = *(const float4*)(src + i);
    *(float4*)&f[4] = *(const float4*)(src + i + 4);
    __half h[8];
    #pragma unroll
    for (int j = 0; j < 8; j++) h[j] = __float2half_rn(f[j]);
    *(uint4*)&g_xh[i] = *(uint4*)h;
}
__global__ void __launch_bounds__(256)
conv_w_kernel(const float* __restrict__ src)
{
    size_t i = ((size_t)blockIdx.x * 256 + threadIdx.x) * 8;
    float f[8];
    *(float4*)&f[0] = *(const float4*)(src + i);
    *(float4*)&f[4] = *(const float4*)(src + i + 4);
    __half h[8];
    #pragma unroll
    for (int j = 0; j < 8; j++) h[j] = __float2half_rn(f[j]);
    *(uint4*)&g_wh[i] = *(uint4*)h;
}

// ---------------------------------------------------------------------------
// fp16 single-term tensor-core GEMM with fused (a, v) epilogue.
// B tile rows interleave z / h_inter: row j -> W[o0p + (j>>1) + (j&1)*HB].
// 2 CTAs/SM: one CTA's barriers/epilogue hide under the other's MMA stream.
// ---------------------------------------------------------------------------
__global__ void __launch_bounds__(256, 2)
gemm_hmma_kernel(const float* __restrict__ b)
{
    extern __shared__ char dynsmem[];
    const uint32_t sbase = smem_u32(dynsmem);

    const int tid = threadIdx.x;
    const int wid = tid >> 5;
    const int l   = tid & 31;
    const int wm  = wid & 3;          // warp m: rows wm*32..+31
    const int wn  = wid >> 2;         // warp n: B rows wn*64..+63
    const int m0  = blockIdx.y * BM;
    const int o0p = blockIdx.x * BNP;

    // cp.async mapping: per tile, thread loads entries e = tid*4 + i (1024 total)
    const __half *sA[4], *sB[4];
    uint32_t dst[4];
    #pragma unroll
    for (int i = 0; i < 4; i++) {
        int e = tid * 4 + i;
        int row = e >> 3, ch = e & 7;
        sA[i] = g_xh + (size_t)(m0 + row) * KB + ch * 8;
        int wrow = (row & 1) ? (HB + o0p + (row >> 1)) : (o0p + (row >> 1));
        sB[i] = g_wh + (size_t)wrow * KB + ch * 8;
        dst[i] = swz(row, ch);
    }

    float acc[2][8][4];
    #pragma unroll
    for (int a0 = 0; a0 < 2; a0++)
        #pragma unroll
        for (int a1 = 0; a1 < 8; a1++)
            #pragma unroll
            for (int a2 = 0; a2 < 4; a2++) acc[a0][a1][a2] = 0.f;

    // prologue: fill PIPE-1 = 2 stages
    #pragma unroll
    for (int s = 0; s < PIPE - 1; s++) {
        uint32_t st = sbase + s * STAGE_BYTES;
        int ko = s * BKE;
        #pragma unroll
        for (int i = 0; i < 4; i++) {
            CP_ASYNC16(st + T_A + dst[i], sA[i] + ko);
            CP_ASYNC16(st + T_B + dst[i], sB[i] + ko);
        }
        CP_COMMIT();
    }

    const int lrow  = l & 15;
    const int lchnk = l >> 4;    // 16B half of the 32B k16 slice

    for (int kt = 0; kt < NKT; kt++) {
        CP_WAIT1();              // oldest stage (kt) complete, <=1 group in flight
        __syncthreads();

        // front-load next-stage loads (target buffer consumed last iteration)
        int ktn = kt + PIPE - 1;
        if (ktn < NKT) {
            uint32_t stl = sbase + (ktn % PIPE) * STAGE_BYTES;
            int ko = ktn * BKE;
            #pragma unroll
            for (int i = 0; i < 4; i++) {
                CP_ASYNC16(stl + T_A + dst[i], sA[i] + ko);
                CP_ASYNC16(stl + T_B + dst[i], sB[i] + ko);
            }
        }
        CP_COMMIT();   // unconditional: keeps wait_group invariant

        const uint32_t st = sbase + (kt % PIPE) * STAGE_BYTES;
        #pragma unroll
        for (int s = 0; s < 4; s++) {           // four k16 steps per stage
            uint32_t a[2][4], bm[4][4];
            #pragma unroll
            for (int mt = 0; mt < 2; mt++) {
                int row = wm * 32 + mt * 16 + lrow;
                ldmx4(a[mt], st + T_A + swz(row, 2 * s + lchnk));
            }
            #pragma unroll
            for (int nt = 0; nt < 4; nt++) {
                int row = wn * 64 + nt * 16 + lrow;
                ldmx4(bm[nt], st + T_B + swz(row, 2 * s + lchnk));
            }
            #pragma unroll
            for (int mt = 0; mt < 2; mt++)
                #pragma unroll
                for (int nt = 0; nt < 4; nt++) {
                    mma_f16(acc[mt][nt * 2],     a[mt], bm[nt][0], bm[nt][2]);
                    mma_f16(acc[mt][nt * 2 + 1], a[mt], bm[nt][1], bm[nt][3]);
                }
        }
    }
    CP_WAIT0();

    // ------------- epilogue: even B-row = z, odd = h_inter of same o
    #pragma unroll
    for (int mt = 0; mt < 2; mt++) {
        #pragma unroll
        for (int nt8 = 0; nt8 < 8; nt8++) {
            int o = o0p + wn * 32 + nt8 * 4 + (l & 3);
            float bz  = __ldg(b + o);
            float bh_ = __ldg(b + HB + o);
            #pragma unroll
            for (int half = 0; half < 2; half++) {
                int m = m0 + wm * 32 + mt * 16 + (l >> 2) + half * 8;
                float z   = acc[mt][nt8][half * 2]     + bz;
                float hin = acc[mt][nt8][half * 2 + 1] + bh_;
                float t   = __expf(-fabsf(z));
                float inv = 1.0f / (1.0f + t);
                float sig = (z >= 0.f) ? inv : t * inv;   // sigmoid(z)
                float av  = (z >= 0.f) ? t * inv : inv;   // sigmoid(-z)
                float gt;
                if (hin >= 0.f) gt = hin + 0.5f;
                else { float t2 = __expf(hin); gt = t2 / (1.f + t2); }
                size_t idx = (size_t)m * HB + o;
                g_a[idx] = av;
                g_v[idx] = sig * gt;
            }
        }
    }
}

// ---------------------------------------------------------------------------
// Scan passes
// ---------------------------------------------------------------------------
__global__ void __launch_bounds__(256)
scan_pass1(void)
{
    int h   = blockIdx.x * 256 + threadIdx.x;
    int seg = blockIdx.y;
    int n   = blockIdx.z;
    size_t base = ((size_t)(n * LB + seg * SEGLEN)) * HB + h;
    float A = 1.f, B = 0.f;
    #pragma unroll 4
    for (int i = 0; i < SEGLEN; i++) {
        float a = g_a[base + (size_t)i * HB];
        float v = g_v[base + (size_t)i * HB];
        B = fmaf(a, B, v);
        A *= a;
    }
    int idx = (n * SEG + seg) * HB + h;
    g_Aseg[idx] = A;
    g_Bseg[idx] = B;
}

__global__ void __launch_bounds__(256)
scan_pass2(const float* __restrict__ hx)
{
    int h = blockIdx.x * 256 + threadIdx.x;
    int n = blockIdx.y;
    float hcur = hx[n * HB + h];
    for (int s = 0; s < SEG; s++) {
        int idx = (n * SEG + s) * HB + h;
        g_Cin[idx] = hcur;
        hcur = fmaf(g_Aseg[idx], hcur, g_Bseg[idx]);
    }
}

__global__ void __launch_bounds__(256)
scan_pass3(float* __restrict__ out)
{
    int h   = blockIdx.x * 256 + threadIdx.x;
    int seg = blockIdx.y;
    int n   = blockIdx.z;
    size_t base = ((size_t)(n * LB + seg * SEGLEN)) * HB + h;
    float hcur = g_Cin[(n * SEG + seg) * HB + h];
    #pragma unroll 4
    for (int i = 0; i < SEGLEN; i++) {
        float a = g_a[base + (size_t)i * HB];
        float v = g_v[base + (size_t)i * HB];
        hcur = fmaf(a, hcur, v);
        out[base + (size_t)i * HB] = hcur;
    }
}

// ---------------------------------------------------------------------------
extern "C" void kernel_launch(void* const* d_in, const int* in_sizes, int n_in,
                              void* d_out, int out_size)
{
    const float *x = nullptr, *W = nullptr, *b = nullptr, *hx = nullptr;
    for (int i = 0; i < n_in; i++) {
        switch (in_sizes[i]) {
            case 33554432: x  = (const float*)d_in[i]; break;
            case 2097152:  W  = (const float*)d_in[i]; break;
            case 2048:     b  = (const float*)d_in[i]; break;
            case 8192:     hx = (const float*)d_in[i]; break;
        }
    }
    float* out = (float*)d_out;

    cudaFuncSetAttribute(gemm_hmma_kernel, cudaFuncAttributeMaxDynamicSharedMemorySize, SMEM_DYN);

    // launches 1-5 before the GEMM (position-based ncu capture lands on GEMM)
    conv_w_kernel<<<(size_t)2 * HB * KB / 8 / 256, 256>>>(W);
    const size_t xq = (size_t)MTOT * KB / 4 / 8 / 256;   // 4096 blocks per quarter
    conv_x_kernel<<<xq, 256>>>(x, 0);
    conv_x_kernel<<<xq, 256>>>(x, 1);
    conv_x_kernel<<<xq, 256>>>(x, 2);
    conv_x_kernel<<<xq, 256>>>(x, 3);

    dim3 gemm_grid(HB / BNP, MTOT / BM);   // (16, 256)
    gemm_hmma_kernel<<<gemm_grid, 256, SMEM_DYN>>>(b);

    scan_pass1<<<dim3(HB / 256, SEG, NB), 256>>>();
    scan_pass2<<<dim3(HB / 256, NB), 256>>>(hx);
    scan_pass3<<<dim3(HB / 256, SEG, NB), 256>>>(out);
}

// round 12
// speedup vs baseline: 4.8720x; 1.0879x over previous
#include <cuda_runtime.h>
#include <cuda_fp16.h>
#include <cstdint>
#include <math.h>

// ---------------- problem dims ----------------
#define NB   8
#define LB   4096
#define HB   1024
#define KB   1024
#define MTOT (NB * LB)          // 32768
#define SEG    32
#define SEGLEN (LB / SEG)       // 128

// ---------------- GEMM tiling -----------------
#define BM 128                  // M rows / CTA
#define BNP 64                  // o-pairs / CTA (B tile = 128 interleaved rows)
#define BKE 64                  // K fp16 elems per stage (128B rows)
#define NKT (KB / BKE)          // 16
#define PIPE 3

// per-stage smem tiles (bytes): 128 rows x 128B each
#define T_A  0
#define T_B  16384
#define STAGE_BYTES 32768
#define SMEM_DYN (PIPE * STAGE_BYTES)   // 96 KB -> 2 CTAs/SM

// ---------------- device scratch ----------------
__device__ __half2 g_av[(size_t)MTOT * HB];    // packed (a, v) = 128 MB
__device__ float  g_Aseg[NB * SEG * HB];
__device__ float  g_Bseg[NB * SEG * HB];
__device__ float  g_Cin [NB * SEG * HB];
__device__ __half g_xh[(size_t)MTOT * KB];     // 64 MB
__device__ __half g_wh[(size_t)2 * HB * KB];   // 4 MB

// ---------------- helpers ----------------
__device__ __forceinline__ uint32_t smem_u32(const void* p) {
    uint32_t a;
    asm("{ .reg .u64 t; cvta.to.shared.u64 t, %1; cvt.u32.u64 %0, t; }" : "=r"(a) : "l"(p));
    return a;
}
// 128B-row tile offset, 16B chunk XOR swizzle (conflict-free ldmatrix + cp.async)
__device__ __forceinline__ uint32_t swz(int row, int ch) {
    return (uint32_t)(row * 128 + ((ch ^ (row & 7)) << 4));
}
#define CP_ASYNC16(sdst, gsrc) \
    asm volatile("cp.async.cg.shared.global [%0], [%1], 16;" :: "r"(sdst), "l"(gsrc))
#define CP_COMMIT() asm volatile("cp.async.commit_group;" ::: "memory")
#define CP_WAIT1()  asm volatile("cp.async.wait_group 1;" ::: "memory")
#define CP_WAIT0()  asm volatile("cp.async.wait_group 0;" ::: "memory")

__device__ __forceinline__ void ldmx4(uint32_t* r, uint32_t addr) {
    asm volatile("ldmatrix.sync.aligned.m8n8.x4.shared.b16 {%0,%1,%2,%3}, [%4];"
        : "=r"(r[0]), "=r"(r[1]), "=r"(r[2]), "=r"(r[3]) : "r"(addr));
}
__device__ __forceinline__ void mma_f16(float* c, const uint32_t* a, uint32_t b0, uint32_t b1) {
    asm volatile("mma.sync.aligned.m16n8k16.row.col.f32.f16.f16.f32 "
        "{%0,%1,%2,%3}, {%4,%5,%6,%7}, {%8,%9}, {%0,%1,%2,%3};"
        : "+f"(c[0]), "+f"(c[1]), "+f"(c[2]), "+f"(c[3])
        : "r"(a[0]), "r"(a[1]), "r"(a[2]), "r"(a[3]), "r"(b0), "r"(b1));
}

// ---------------------------------------------------------------------------
// Conversions to fp16 (rn)
// ---------------------------------------------------------------------------
__global__ void __launch_bounds__(256)
conv_x_kernel(const float* __restrict__ src)
{
    size_t i = ((size_t)blockIdx.x * 256 + threadIdx.x) * 8;
    float f[8];
    *(float4*)&f[0] = *(const float4*)(src + i);
    *(float4*)&f[4] = *(const float4*)(src + i + 4);
    __half h[8];
    #pragma unroll
    for (int j = 0; j < 8; j++) h[j] = __float2half_rn(f[j]);
    *(uint4*)&g_xh[i] = *(uint4*)h;
}
__global__ void __launch_bounds__(256)
conv_w_kernel(const float* __restrict__ src)
{
    size_t i = ((size_t)blockIdx.x * 256 + threadIdx.x) * 8;
    float f[8];
    *(float4*)&f[0] = *(const float4*)(src + i);
    *(float4*)&f[4] = *(const float4*)(src + i + 4);
    __half h[8];
    #pragma unroll
    for (int j = 0; j < 8; j++) h[j] = __float2half_rn(f[j]);
    *(uint4*)&g_wh[i] = *(uint4*)h;
}

// ---------------------------------------------------------------------------
// fp16 single-term tensor-core GEMM with fused (a, v) epilogue (fp16 packed).
// B tile rows interleave z / h_inter: row j -> W[o0p + (j>>1) + (j&1)*HB].
// ---------------------------------------------------------------------------
__global__ void __launch_bounds__(256, 2)
gemm_hmma_kernel(const float* __restrict__ b)
{
    extern __shared__ char dynsmem[];
    const uint32_t sbase = smem_u32(dynsmem);

    const int tid = threadIdx.x;
    const int wid = tid >> 5;
    const int l   = tid & 31;
    const int wm  = wid & 3;          // warp m: rows wm*32..+31
    const int wn  = wid >> 2;         // warp n: B rows wn*64..+63
    const int m0  = blockIdx.y * BM;
    const int o0p = blockIdx.x * BNP;

    // cp.async mapping: per tile, thread loads entries e = tid*4 + i (1024 total)
    const __half *sA[4], *sB[4];
    uint32_t dst[4];
    #pragma unroll
    for (int i = 0; i < 4; i++) {
        int e = tid * 4 + i;
        int row = e >> 3, ch = e & 7;
        sA[i] = g_xh + (size_t)(m0 + row) * KB + ch * 8;
        int wrow = (row & 1) ? (HB + o0p + (row >> 1)) : (o0p + (row >> 1));
        sB[i] = g_wh + (size_t)wrow * KB + ch * 8;
        dst[i] = swz(row, ch);
    }

    float acc[2][8][4];
    #pragma unroll
    for (int a0 = 0; a0 < 2; a0++)
        #pragma unroll
        for (int a1 = 0; a1 < 8; a1++)
            #pragma unroll
            for (int a2 = 0; a2 < 4; a2++) acc[a0][a1][a2] = 0.f;

    // prologue: fill PIPE-1 = 2 stages
    #pragma unroll
    for (int s = 0; s < PIPE - 1; s++) {
        uint32_t st = sbase + s * STAGE_BYTES;
        int ko = s * BKE;
        #pragma unroll
        for (int i = 0; i < 4; i++) {
            CP_ASYNC16(st + T_A + dst[i], sA[i] + ko);
            CP_ASYNC16(st + T_B + dst[i], sB[i] + ko);
        }
        CP_COMMIT();
    }

    const int lrow  = l & 15;
    const int lchnk = l >> 4;    // 16B half of the 32B k16 slice

    for (int kt = 0; kt < NKT; kt++) {
        CP_WAIT1();              // oldest stage (kt) complete
        __syncthreads();

        // front-load next-stage loads (target buffer consumed last iteration)
        int ktn = kt + PIPE - 1;
        if (ktn < NKT) {
            uint32_t stl = sbase + (ktn % PIPE) * STAGE_BYTES;
            int ko = ktn * BKE;
            #pragma unroll
            for (int i = 0; i < 4; i++) {
                CP_ASYNC16(stl + T_A + dst[i], sA[i] + ko);
                CP_ASYNC16(stl + T_B + dst[i], sB[i] + ko);
            }
        }
        CP_COMMIT();   // unconditional: keeps wait_group invariant

        const uint32_t st = sbase + (kt % PIPE) * STAGE_BYTES;
        #pragma unroll
        for (int s = 0; s < 4; s++) {           // four k16 steps per stage
            uint32_t a[2][4], bm[4][4];
            #pragma unroll
            for (int mt = 0; mt < 2; mt++) {
                int row = wm * 32 + mt * 16 + lrow;
                ldmx4(a[mt], st + T_A + swz(row, 2 * s + lchnk));
            }
            #pragma unroll
            for (int nt = 0; nt < 4; nt++) {
                int row = wn * 64 + nt * 16 + lrow;
                ldmx4(bm[nt], st + T_B + swz(row, 2 * s + lchnk));
            }
            #pragma unroll
            for (int mt = 0; mt < 2; mt++)
                #pragma unroll
                for (int nt = 0; nt < 4; nt++) {
                    mma_f16(acc[mt][nt * 2],     a[mt], bm[nt][0], bm[nt][2]);
                    mma_f16(acc[mt][nt * 2 + 1], a[mt], bm[nt][1], bm[nt][3]);
                }
        }
    }
    CP_WAIT0();

    // ------------- epilogue: even B-row = z, odd = h_inter of same o
    #pragma unroll
    for (int mt = 0; mt < 2; mt++) {
        #pragma unroll
        for (int nt8 = 0; nt8 < 8; nt8++) {
            int o = o0p + wn * 32 + nt8 * 4 + (l & 3);
            float bz  = __ldg(b + o);
            float bh_ = __ldg(b + HB + o);
            #pragma unroll
            for (int half = 0; half < 2; half++) {
                int m = m0 + wm * 32 + mt * 16 + (l >> 2) + half * 8;
                float z   = acc[mt][nt8][half * 2]     + bz;
                float hin = acc[mt][nt8][half * 2 + 1] + bh_;
                float t   = __expf(-fabsf(z));
                float inv = 1.0f / (1.0f + t);
                float sig = (z >= 0.f) ? inv : t * inv;   // sigmoid(z)
                float av  = (z >= 0.f) ? t * inv : inv;   // sigmoid(-z)
                float gt;
                if (hin >= 0.f) gt = hin + 0.5f;
                else { float t2 = __expf(hin); gt = t2 / (1.f + t2); }
                size_t idx = (size_t)m * HB + o;
                g_av[idx] = __floats2half2_rn(av, sig * gt);
            }
        }
    }
}

// ---------------------------------------------------------------------------
// Scan passes (fp16 packed a/v, fp32 accumulation)
// ---------------------------------------------------------------------------
__global__ void __launch_bounds__(256)
scan_pass1(void)
{
    int h   = blockIdx.x * 256 + threadIdx.x;
    int seg = blockIdx.y;
    int n   = blockIdx.z;
    size_t base = ((size_t)(n * LB + seg * SEGLEN)) * HB + h;
    float A = 1.f, B = 0.f;
    #pragma unroll 4
    for (int i = 0; i < SEGLEN; i++) {
        float2 av = __half22float2(g_av[base + (size_t)i * HB]);
        B = fmaf(av.x, B, av.y);
        A *= av.x;
    }
    int idx = (n * SEG + seg) * HB + h;
    g_Aseg[idx] = A;
    g_Bseg[idx] = B;
}

__global__ void __launch_bounds__(256)
scan_pass2(const float* __restrict__ hx)
{
    int h = blockIdx.x * 256 + threadIdx.x;
    int n = blockIdx.y;
    float hcur = hx[n * HB + h];
    for (int s = 0; s < SEG; s++) {
        int idx = (n * SEG + s) * HB + h;
        g_Cin[idx] = hcur;
        hcur = fmaf(g_Aseg[idx], hcur, g_Bseg[idx]);
    }
}

__global__ void __launch_bounds__(256)
scan_pass3(float* __restrict__ out)
{
    int h   = blockIdx.x * 256 + threadIdx.x;
    int seg = blockIdx.y;
    int n   = blockIdx.z;
    size_t base = ((size_t)(n * LB + seg * SEGLEN)) * HB + h;
    float hcur = g_Cin[(n * SEG + seg) * HB + h];
    #pragma unroll 4
    for (int i = 0; i < SEGLEN; i++) {
        float2 av = __half22float2(g_av[base + (size_t)i * HB]);
        hcur = fmaf(av.x, hcur, av.y);
        out[base + (size_t)i * HB] = hcur;
    }
}

// ---------------------------------------------------------------------------
extern "C" void kernel_launch(void* const* d_in, const int* in_sizes, int n_in,
                              void* d_out, int out_size)
{
    const float *x = nullptr, *W = nullptr, *b = nullptr, *hx = nullptr;
    for (int i = 0; i < n_in; i++) {
        switch (in_sizes[i]) {
            case 33554432: x  = (const float*)d_in[i]; break;
            case 2097152:  W  = (const float*)d_in[i]; break;
            case 2048:     b  = (const float*)d_in[i]; break;
            case 8192:     hx = (const float*)d_in[i]; break;
        }
    }
    float* out = (float*)d_out;

    cudaFuncSetAttribute(gemm_hmma_kernel, cudaFuncAttributeMaxDynamicSharedMemorySize, SMEM_DYN);

    conv_w_kernel<<<(size_t)2 * HB * KB / 8 / 256, 256>>>(W);
    conv_x_kernel<<<(size_t)MTOT * KB / 8 / 256, 256>>>(x);   // 16384 blocks

    dim3 gemm_grid(HB / BNP, MTOT / BM);   // (16, 256)
    gemm_hmma_kernel<<<gemm_grid, 256, SMEM_DYN>>>(b);

    scan_pass1<<<dim3(HB / 256, SEG, NB), 256>>>();
    scan_pass2<<<dim3(HB / 256, NB), 256>>>(hx);
    scan_pass3<<<dim3(HB / 256, SEG, NB), 256>>>(out);
}